// round 3
// baseline (speedup 1.0000x reference)
#include <cuda_runtime.h>

#define CB 4
#define CS 1500
#define CHID 1024
#define CNH 16
#define CDH 64
#define NREL 129           // 2K+1, K=64
#define MROWS (CB*CS)      // 6000

// ---------------- scratch (device globals; no allocation allowed) -------------
__device__ float g_q[CB*CNH*CS*CDH];       // [B,NH,S,DH]
__device__ float g_k[CB*CNH*CS*CDH];
__device__ float g_v[CB*CNH*CS*CDH];
__device__ float g_hidden[CB*CS*CHID];     // [B,S,HID] concat-head output

// ============================================================================
// Projection GEMM: C[b,n,s,d] = sum_h X[b,s,h] * W[n,h,d] + bias[n,d]
// X viewed as [6000,1024] row-major. 128x128x16 tile, 8x8 per thread.
// ============================================================================
__global__ __launch_bounds__(256) void gemm_proj(
    const float* __restrict__ X, const float* __restrict__ W,
    const float* __restrict__ bias, float* __restrict__ out)
{
    __shared__ float As[128][16];
    __shared__ float Bs[16][128];
    int tid = threadIdx.x;
    int tx = tid & 15, ty = tid >> 4;
    int m0 = blockIdx.x * 128;
    int n0 = blockIdx.y * 128;
    float acc[8][8];
    #pragma unroll
    for (int i = 0; i < 8; i++)
        #pragma unroll
        for (int j = 0; j < 8; j++) acc[i][j] = 0.f;

    for (int k0 = 0; k0 < CHID; k0 += 16) {
        #pragma unroll
        for (int p = 0; p < 2; p++) {
            int fidx = tid + p * 256;          // 0..511 float4 slots
            int mm = fidx >> 2;
            int kk = (fidx & 3) << 2;
            int m = m0 + mm;
            float4 val = make_float4(0.f, 0.f, 0.f, 0.f);
            if (m < MROWS) val = *(const float4*)(X + (size_t)m * CHID + k0 + kk);
            *(float4*)(&As[mm][kk]) = val;
        }
        #pragma unroll
        for (int p = 0; p < 2; p++) {
            int fidx = tid + p * 256;
            int r = fidx >> 5;
            int c = (fidx & 31) << 2;
            int col = n0 + c;
            int n = col >> 6, d = col & 63;
            float4 val = *(const float4*)(W + (size_t)n * (CHID * CDH)
                                            + (size_t)(k0 + r) * CDH + d);
            *(float4*)(&Bs[r][c]) = val;
        }
        __syncthreads();
        #pragma unroll
        for (int kk = 0; kk < 16; kk++) {
            float a[8], bb[8];
            #pragma unroll
            for (int i = 0; i < 8; i++) a[i] = As[ty * 8 + i][kk];
            float4 b0 = *(float4*)(&Bs[kk][tx * 8]);
            float4 b1 = *(float4*)(&Bs[kk][tx * 8 + 4]);
            bb[0] = b0.x; bb[1] = b0.y; bb[2] = b0.z; bb[3] = b0.w;
            bb[4] = b1.x; bb[5] = b1.y; bb[6] = b1.z; bb[7] = b1.w;
            #pragma unroll
            for (int i = 0; i < 8; i++)
                #pragma unroll
                for (int j = 0; j < 8; j++) acc[i][j] += a[i] * bb[j];
        }
        __syncthreads();
    }
    #pragma unroll
    for (int i = 0; i < 8; i++) {
        int m = m0 + ty * 8 + i;
        if (m >= MROWS) continue;
        int bidx = m / CS, s = m % CS;
        #pragma unroll
        for (int j = 0; j < 8; j++) {
            int col = n0 + tx * 8 + j;
            int n = col >> 6, d = col & 63;
            out[(((size_t)(bidx * CNH + n)) * CS + s) * CDH + d] = acc[i][j] + bias[col];
        }
    }
}

// ============================================================================
// Output GEMM: out[m, :] = hidden[m, :] @ W_fc + b_fc
// ============================================================================
__global__ __launch_bounds__(256) void gemm_fc(
    const float* __restrict__ X, const float* __restrict__ W,
    const float* __restrict__ bias, float* __restrict__ out)
{
    __shared__ float As[128][16];
    __shared__ float Bs[16][128];
    int tid = threadIdx.x;
    int tx = tid & 15, ty = tid >> 4;
    int m0 = blockIdx.x * 128;
    int n0 = blockIdx.y * 128;
    float acc[8][8];
    #pragma unroll
    for (int i = 0; i < 8; i++)
        #pragma unroll
        for (int j = 0; j < 8; j++) acc[i][j] = 0.f;

    for (int k0 = 0; k0 < CHID; k0 += 16) {
        #pragma unroll
        for (int p = 0; p < 2; p++) {
            int fidx = tid + p * 256;
            int mm = fidx >> 2;
            int kk = (fidx & 3) << 2;
            int m = m0 + mm;
            float4 val = make_float4(0.f, 0.f, 0.f, 0.f);
            if (m < MROWS) val = *(const float4*)(X + (size_t)m * CHID + k0 + kk);
            *(float4*)(&As[mm][kk]) = val;
        }
        #pragma unroll
        for (int p = 0; p < 2; p++) {
            int fidx = tid + p * 256;
            int r = fidx >> 5;
            int c = (fidx & 31) << 2;
            float4 val = *(const float4*)(W + (size_t)(k0 + r) * CHID + n0 + c);
            *(float4*)(&Bs[r][c]) = val;
        }
        __syncthreads();
        #pragma unroll
        for (int kk = 0; kk < 16; kk++) {
            float a[8], bb[8];
            #pragma unroll
            for (int i = 0; i < 8; i++) a[i] = As[ty * 8 + i][kk];
            float4 b0 = *(float4*)(&Bs[kk][tx * 8]);
            float4 b1 = *(float4*)(&Bs[kk][tx * 8 + 4]);
            bb[0] = b0.x; bb[1] = b0.y; bb[2] = b0.z; bb[3] = b0.w;
            bb[4] = b1.x; bb[5] = b1.y; bb[6] = b1.z; bb[7] = b1.w;
            #pragma unroll
            for (int i = 0; i < 8; i++)
                #pragma unroll
                for (int j = 0; j < 8; j++) acc[i][j] += a[i] * bb[j];
        }
        __syncthreads();
    }
    #pragma unroll
    for (int i = 0; i < 8; i++) {
        int m = m0 + ty * 8 + i;
        if (m >= MROWS) continue;
        #pragma unroll
        for (int j = 0; j < 8; j++) {
            int col = n0 + tx * 8 + j;
            out[(size_t)m * CHID + col] = acc[i][j] + bias[col];
        }
    }
}

// ============================================================================
// Flash attention with Shaw relative position bias.
// One block = (b, head, q-tile of 64). Online softmax, single pass over K.
//   s[q,k]   = (q.k + r[q, clip(k-q)+64]) / 8,   r computed in-smem from Q tile
//   O accum += p @ V  (+ banded pos_v term for near-diagonal tiles)
//   PL/PH    = clipped probability mass -> pos_v[0]/pos_v[128] in epilogue
// ============================================================================
#define SQ_STRIDE 68
#define SR_STRIDE 132
#define FLASH_SMEM_FLOATS (4*64*SQ_STRIDE + 64*SR_STRIDE)

__global__ __launch_bounds__(256, 2) void flash_kernel(
    const float* __restrict__ posk, const float* __restrict__ posv)
{
    extern __shared__ float sm[];
    float* Qs  = sm;                              // [64][68]
    float* Rs  = Qs + 64 * SQ_STRIDE;             // [64][132]
    float* Ks  = Rs + 64 * SR_STRIDE;             // [64][68]
    float* Vs  = Ks + 64 * SQ_STRIDE;             // [64][68]
    float* Ps  = Vs + 64 * SQ_STRIDE;             // [64][68]
    float* PKs = Ks;                              // prologue overlay [129][68]

    int qt = blockIdx.x, hn = blockIdx.y, bb = blockIdx.z;
    int q0 = qt * 64;
    size_t head_off = ((size_t)(bb * CNH + hn)) * CS * CDH;
    const float* qbase = g_q + head_off;
    const float* kbase = g_k + head_off;
    const float* vbase = g_v + head_off;

    int tid = threadIdx.x;
    int tx = tid & 15, ty = tid >> 4;

    // ---- load Q tile (zero-pad rows >= S) ----
    for (int idx = tid; idx < 64 * 64; idx += 256) {
        int r = idx >> 6, d = idx & 63;
        int qg = q0 + r;
        Qs[r * SQ_STRIDE + d] = (qg < CS) ? qbase[qg * CDH + d] : 0.f;
    }
    // ---- load pos_k into overlay region ----
    for (int idx = tid; idx < NREL * 64; idx += 256) {
        int j = idx >> 6, d = idx & 63;
        PKs[j * SQ_STRIDE + d] = posk[idx];
    }
    __syncthreads();

    // ---- Rs[q][j] = Q[q,:] . pos_k[j,:]  (relative key bias lookup table) ----
    for (int t = tid; t < 64 * 33; t += 256) {
        int qq = t / 33;
        int jg = t - qq * 33;
        int j0 = jg * 4;
        const float4* q4 = (const float4*)(Qs + qq * SQ_STRIDE);
        if (jg < 32) {
            const float4* p0 = (const float4*)(PKs + (j0 + 0) * SQ_STRIDE);
            const float4* p1 = (const float4*)(PKs + (j0 + 1) * SQ_STRIDE);
            const float4* p2 = (const float4*)(PKs + (j0 + 2) * SQ_STRIDE);
            const float4* p3 = (const float4*)(PKs + (j0 + 3) * SQ_STRIDE);
            float a0 = 0.f, a1 = 0.f, a2 = 0.f, a3 = 0.f;
            #pragma unroll
            for (int d4 = 0; d4 < 16; d4++) {
                float4 qv = q4[d4];
                float4 x;
                x = p0[d4]; a0 += qv.x*x.x + qv.y*x.y + qv.z*x.z + qv.w*x.w;
                x = p1[d4]; a1 += qv.x*x.x + qv.y*x.y + qv.z*x.z + qv.w*x.w;
                x = p2[d4]; a2 += qv.x*x.x + qv.y*x.y + qv.z*x.z + qv.w*x.w;
                x = p3[d4]; a3 += qv.x*x.x + qv.y*x.y + qv.z*x.z + qv.w*x.w;
            }
            Rs[qq * SR_STRIDE + j0 + 0] = a0;
            Rs[qq * SR_STRIDE + j0 + 1] = a1;
            Rs[qq * SR_STRIDE + j0 + 2] = a2;
            Rs[qq * SR_STRIDE + j0 + 3] = a3;
        } else {                       // j0 == 128 (last rel position)
            const float4* p0 = (const float4*)(PKs + 128 * SQ_STRIDE);
            float a0 = 0.f;
            #pragma unroll
            for (int d4 = 0; d4 < 16; d4++) {
                float4 qv = q4[d4];
                float4 x = p0[d4];
                a0 += qv.x*x.x + qv.y*x.y + qv.z*x.z + qv.w*x.w;
            }
            Rs[qq * SR_STRIDE + 128] = a0;
        }
    }

    // ---- per-thread online softmax state: rows ty*4+i, cols tx*4+j ----
    float m_i[4], l_i[4], PL[4], PH[4], O[4][4];
    #pragma unroll
    for (int i = 0; i < 4; i++) {
        m_i[i] = -1e30f; l_i[i] = 0.f; PL[i] = 0.f; PH[i] = 0.f;
        #pragma unroll
        for (int j = 0; j < 4; j++) O[i][j] = 0.f;
    }

    const int NKT = (CS + 63) / 64;        // 24
    for (int kt = 0; kt < NKT; kt++) {
        __syncthreads();                   // protect Ks/Vs/Ps (and prologue overlay)
        for (int idx = tid; idx < 64 * 64; idx += 256) {
            int r = idx >> 6, d = idx & 63;
            int kg = kt * 64 + r;
            float kv = 0.f, vv = 0.f;
            if (kg < CS) { kv = kbase[kg * CDH + d]; vv = vbase[kg * CDH + d]; }
            Ks[r * SQ_STRIDE + d] = kv;
            Vs[r * SQ_STRIDE + d] = vv;
        }
        __syncthreads();

        // ---- S = Q K^T ----
        float s[4][4];
        #pragma unroll
        for (int i = 0; i < 4; i++)
            #pragma unroll
            for (int j = 0; j < 4; j++) s[i][j] = 0.f;
        #pragma unroll 8
        for (int d = 0; d < 64; d++) {
            float a[4], bv[4];
            #pragma unroll
            for (int i = 0; i < 4; i++) a[i] = Qs[(ty * 4 + i) * SQ_STRIDE + d];
            #pragma unroll
            for (int j = 0; j < 4; j++) bv[j] = Ks[(tx * 4 + j) * SQ_STRIDE + d];
            #pragma unroll
            for (int i = 0; i < 4; i++)
                #pragma unroll
                for (int j = 0; j < 4; j++) s[i][j] += a[i] * bv[j];
        }

        // ---- add relative-key bias, scale, mask out-of-range k ----
        #pragma unroll
        for (int i = 0; i < 4; i++) {
            int qg = q0 + ty * 4 + i;
            #pragma unroll
            for (int j = 0; j < 4; j++) {
                int kg = kt * 64 + tx * 4 + j;
                int delta = kg - qg;
                int jc = delta < -64 ? 0 : (delta > 64 ? 128 : delta + 64);
                float val = (s[i][j] + Rs[(ty * 4 + i) * SR_STRIDE + jc]) * 0.125f;
                s[i][j] = (kg < CS) ? val : -1e30f;
            }
        }

        int diff = kt * 64 - q0;
        bool band = (diff >= -64 && diff <= 64);

        // ---- online softmax update ----
        #pragma unroll
        for (int i = 0; i < 4; i++) {
            float tmax = fmaxf(fmaxf(s[i][0], s[i][1]), fmaxf(s[i][2], s[i][3]));
            #pragma unroll
            for (int off = 8; off >= 1; off >>= 1)
                tmax = fmaxf(tmax, __shfl_xor_sync(0xffffffffu, tmax, off));
            float mnew  = fmaxf(m_i[i], tmax);
            float alpha = __expf(m_i[i] - mnew);
            m_i[i] = mnew;
            int qg = q0 + ty * 4 + i;
            float psum = 0.f, plo = 0.f, phi = 0.f;
            #pragma unroll
            for (int j = 0; j < 4; j++) {
                float p = __expf(s[i][j] - mnew);
                s[i][j] = p;
                psum += p;
                if (band) {
                    int delta = (kt * 64 + tx * 4 + j) - qg;
                    if (delta <= -64) plo += p;
                    if (delta >=  64) phi += p;
                }
            }
            #pragma unroll
            for (int off = 8; off >= 1; off >>= 1)
                psum += __shfl_xor_sync(0xffffffffu, psum, off);
            if (band) {
                #pragma unroll
                for (int off = 8; off >= 1; off >>= 1) {
                    plo += __shfl_xor_sync(0xffffffffu, plo, off);
                    phi += __shfl_xor_sync(0xffffffffu, phi, off);
                }
            } else if (diff < -64) { plo = psum; phi = 0.f; }
            else                   { phi = psum; plo = 0.f; }

            l_i[i] = l_i[i] * alpha + psum;
            PL[i]  = PL[i]  * alpha + plo;
            PH[i]  = PH[i]  * alpha + phi;
            #pragma unroll
            for (int j = 0; j < 4; j++) O[i][j] *= alpha;
            #pragma unroll
            for (int j = 0; j < 4; j++)
                Ps[(ty * 4 + i) * SQ_STRIDE + tx * 4 + j] = s[i][j];
        }
        __syncthreads();

        // ---- O += P @ V ----
        #pragma unroll 8
        for (int kk = 0; kk < 64; kk++) {
            float a[4], v[4];
            #pragma unroll
            for (int i = 0; i < 4; i++) a[i] = Ps[(ty * 4 + i) * SQ_STRIDE + kk];
            #pragma unroll
            for (int j = 0; j < 4; j++) v[j] = Vs[kk * SQ_STRIDE + tx * 4 + j];
            #pragma unroll
            for (int i = 0; i < 4; i++)
                #pragma unroll
                for (int j = 0; j < 4; j++) O[i][j] += a[i] * v[j];
        }

        // ---- banded relative-value contribution (near-diagonal tiles only) ----
        if (band) {
            #pragma unroll 4
            for (int kk = 0; kk < 64; kk++) {
                int kg = kt * 64 + kk;
                #pragma unroll
                for (int i = 0; i < 4; i++) {
                    int delta = kg - (q0 + ty * 4 + i);
                    if (delta > -64 && delta < 64) {
                        float p = Ps[(ty * 4 + i) * SQ_STRIDE + kk];
                        float4 pv = *(const float4*)(posv + (delta + 64) * 64 + tx * 4);
                        O[i][0] += p * pv.x; O[i][1] += p * pv.y;
                        O[i][2] += p * pv.z; O[i][3] += p * pv.w;
                    }
                }
            }
        }
    }

    // ---- epilogue: normalize, add clipped-boundary pos_v mass, write concat ----
    #pragma unroll
    for (int i = 0; i < 4; i++) {
        int qg = q0 + ty * 4 + i;
        if (qg >= CS) continue;
        float inv = 1.f / l_i[i];
        int dg = tx * 4;
        float4 pv0   = *(const float4*)(posv + 0 * 64 + dg);
        float4 pv128 = *(const float4*)(posv + 128 * 64 + dg);
        float4 res;
        res.x = (O[i][0] + PL[i] * pv0.x + PH[i] * pv128.x) * inv;
        res.y = (O[i][1] + PL[i] * pv0.y + PH[i] * pv128.y) * inv;
        res.z = (O[i][2] + PL[i] * pv0.z + PH[i] * pv128.z) * inv;
        res.w = (O[i][3] + PL[i] * pv0.w + PH[i] * pv128.w) * inv;
        *(float4*)(g_hidden + ((size_t)(bb * CS + qg)) * CHID + hn * 64 + dg) = res;
    }
}

// ============================================================================
extern "C" void kernel_launch(void* const* d_in, const int* in_sizes, int n_in,
                              void* d_out, int out_size)
{
    const float* query = (const float*)d_in[0];
    const float* key   = (const float*)d_in[1];
    const float* value = (const float*)d_in[2];
    const float* Wq    = (const float*)d_in[3];
    const float* bq    = (const float*)d_in[4];
    const float* Wk    = (const float*)d_in[5];
    const float* bk    = (const float*)d_in[6];
    const float* Wv    = (const float*)d_in[7];
    const float* bv    = (const float*)d_in[8];
    const float* posk  = (const float*)d_in[9];
    const float* posv  = (const float*)d_in[10];
    const float* Wfc   = (const float*)d_in[11];
    const float* bfc   = (const float*)d_in[12];
    float* out = (float*)d_out;

    float *gq, *gk, *gv, *gh;
    cudaGetSymbolAddress((void**)&gq, g_q);
    cudaGetSymbolAddress((void**)&gk, g_k);
    cudaGetSymbolAddress((void**)&gv, g_v);
    cudaGetSymbolAddress((void**)&gh, g_hidden);

    dim3 gp((MROWS + 127) / 128, CHID / 128);
    gemm_proj<<<gp, 256>>>(query, Wq, bq, gq);
    gemm_proj<<<gp, 256>>>(key,   Wk, bk, gk);
    gemm_proj<<<gp, 256>>>(value, Wv, bv, gv);

    int smem_bytes = FLASH_SMEM_FLOATS * (int)sizeof(float);   // 103,424 B
    cudaFuncSetAttribute(flash_kernel,
                         cudaFuncAttributeMaxDynamicSharedMemorySize, smem_bytes);
    flash_kernel<<<dim3((CS + 63) / 64, CNH, CB), 256, smem_bytes>>>(posk, posv);

    gemm_fc<<<gp, 256>>>(gh, Wfc, bfc, out);
}

// round 7
// speedup vs baseline: 1.2682x; 1.2682x over previous
#include <cuda_runtime.h>
#include <cuda_bf16.h>
#include <stdint.h>

#define CB 4
#define CS 1500
#define CHID 1024
#define CNH 16
#define CDH 64
#define NREL 129           // 2K+1, K=64
#define MROWS (CB*CS)      // 6000

// ---------------- scratch (device globals; no allocation allowed) -------------
__device__ float g_q[CB*CNH*CS*CDH];       // [B,NH,S,DH]
__device__ float g_k[CB*CNH*CS*CDH];
__device__ float g_v[CB*CNH*CS*CDH];
__device__ float g_hidden[CB*CS*CHID];     // [B,S,HID] concat-head output
// bf16 split-precision staging (reused sequentially across GEMMs)
__device__ __align__(16) __nv_bfloat16 g_xh[MROWS*CHID];
__device__ __align__(16) __nv_bfloat16 g_xl[MROWS*CHID];
__device__ __align__(16) __nv_bfloat16 g_wh[CHID*CHID];   // [N=1024 rows][K=1024] K-major
__device__ __align__(16) __nv_bfloat16 g_wl[CHID*CHID];

// ============================================================================
// Warp-level MMA helpers (base-PTX, legal on compute_103)
// ============================================================================
__device__ __forceinline__ uint32_t smem_u32(const void* p) {
    uint32_t a;
    asm("{ .reg .u64 t; cvta.to.shared.u64 t, %1; cvt.u32.u64 %0, t; }" : "=r"(a) : "l"(p));
    return a;
}
__device__ __forceinline__ void ldsm4(uint32_t* r, uint32_t a) {
    asm volatile("ldmatrix.sync.aligned.m8n8.x4.shared.b16 {%0,%1,%2,%3}, [%4];"
                 : "=r"(r[0]), "=r"(r[1]), "=r"(r[2]), "=r"(r[3]) : "r"(a));
}
__device__ __forceinline__ void mma16816(float* c, const uint32_t* a, const uint32_t* b) {
    asm volatile(
        "mma.sync.aligned.m16n8k16.row.col.f32.bf16.bf16.f32 "
        "{%0,%1,%2,%3}, {%4,%5,%6,%7}, {%8,%9}, {%0,%1,%2,%3};"
        : "+f"(c[0]), "+f"(c[1]), "+f"(c[2]), "+f"(c[3])
        : "r"(a[0]), "r"(a[1]), "r"(a[2]), "r"(a[3]), "r"(b[0]), "r"(b[1]));
}

// ============================================================================
// Split-precision conversion kernels
// ============================================================================
__global__ void cvt_split(const float* __restrict__ x,
                          __nv_bfloat16* __restrict__ hi, __nv_bfloat16* __restrict__ lo,
                          int n) {
    int i = blockIdx.x * blockDim.x + threadIdx.x;
    if (i < n) {
        float v = x[i];
        __nv_bfloat16 h = __float2bfloat16(v);
        hi[i] = h;
        lo[i] = __float2bfloat16(v - __bfloat162float(h));
    }
}
// proj weight: Wb[col][k] = W[n=col>>6][k][d=col&63]  (stacked heads -> K-major)
__global__ void cvt_w_proj(const float* __restrict__ W,
                           __nv_bfloat16* __restrict__ hi, __nv_bfloat16* __restrict__ lo) {
    int i = blockIdx.x * blockDim.x + threadIdx.x;
    if (i < CHID * CHID) {
        int col = i >> 10, k = i & 1023;
        int n = col >> 6, d = col & 63;
        float v = W[((size_t)n * CHID + k) * CDH + d];
        __nv_bfloat16 h = __float2bfloat16(v);
        hi[i] = h;
        lo[i] = __float2bfloat16(v - __bfloat162float(h));
    }
}
// fc weight: Wb[col][k] = Wfc[k][col]
__global__ void cvt_w_fc(const float* __restrict__ W,
                         __nv_bfloat16* __restrict__ hi, __nv_bfloat16* __restrict__ lo) {
    int i = blockIdx.x * blockDim.x + threadIdx.x;
    if (i < CHID * CHID) {
        int col = i >> 10, k = i & 1023;
        float v = W[(size_t)k * CHID + col];
        __nv_bfloat16 h = __float2bfloat16(v);
        hi[i] = h;
        lo[i] = __float2bfloat16(v - __bfloat162float(h));
    }
}

// ============================================================================
// mma.sync split-bf16 GEMM: C[m0:m0+128, n0:n0+128] = X @ W^T + bias
//   X: [6000,1024] K-major bf16 (hi/lo);  W: [1024 N-rows][1024 K] bf16 (hi/lo)
//   C += Ah*Bh + Ah*Bl + Al*Bh  (fp32 accum; drops only eps^2 term)
// Block 128x128, 8 warps 2x4 (warp tile 64x32), K-chunks of 64.
// MODE 0: proj scatter to [B,NH,S,DH];  MODE 1: plain [M,1024] store
// ============================================================================
#define SPITCH 144                       // 72 bf16 per row (64 data + 8 pad)
#define TILE_BYTES (128 * SPITCH)        // 18432
#define GEMM_SMEM_BYTES (4 * TILE_BYTES) // 73728: Ah, Al, Bh, Bl

template<int MODE>
__global__ __launch_bounds__(256, 1) void gemm_mma(
    const __nv_bfloat16* __restrict__ Xh, const __nv_bfloat16* __restrict__ Xl,
    const __nv_bfloat16* __restrict__ Wh, const __nv_bfloat16* __restrict__ Wl,
    const float* __restrict__ bias, float* __restrict__ out)
{
    extern __shared__ char smem[];
    uint32_t sbase = smem_u32(smem);
    int tid = threadIdx.x;
    int wid = tid >> 5, lid = tid & 31;
    int wm = wid & 1, wn = wid >> 1;     // 2 x 4 warp grid
    int m0 = blockIdx.x * 128;
    int n0 = blockIdx.y * 128;

    float C[4][4][4];                     // [mfrag][nfrag][c0..c3]
    #pragma unroll
    for (int i = 0; i < 4; i++)
        #pragma unroll
        for (int j = 0; j < 4; j++)
            #pragma unroll
            for (int r = 0; r < 4; r++) C[i][j][r] = 0.f;

    // precomputed ldmatrix smem addresses (lane-dependent, chunk-invariant)
    // A tiles: row = wm*64 + i*16 + (lid&15), koff8 = (lid>>4)*8
    uint32_t a_row = wm * 64 + (lid & 15);
    uint32_t a_koff = (lid >> 4) * 8;
    // B tiles (x4 covers 2 nfrags): t = lid>>3
    uint32_t b_n = wn * 32 + ((lid >> 4) * 8) + (lid & 7); // lanes16+ -> +8 rows
    uint32_t b_koff = ((lid >> 3) & 1) * 8;

    const int NCHUNK = CHID / 64;        // 16
    for (int c = 0; c < NCHUNK; c++) {
        __syncthreads();
        // ---- load 4 tiles: 128 rows x 64 bf16, padded rows ----
        #pragma unroll
        for (int t = 0; t < 4; t++) {
            const __nv_bfloat16* src = (t == 0) ? Xh : (t == 1) ? Xl : (t == 2) ? Wh : Wl;
            const bool isA = (t < 2);
            char* db = smem + t * TILE_BYTES;
            #pragma unroll
            for (int p = 0; p < 4; p++) {
                int slot = tid + p * 256;            // 0..1023
                int row = slot >> 3, i8 = slot & 7;
                int gr = (isA ? m0 : n0) + row;
                uint4 v = make_uint4(0, 0, 0, 0);
                if (!isA || gr < MROWS)
                    v = ((const uint4*)(src + (size_t)gr * CHID + c * 64))[i8];
                *(uint4*)(db + row * SPITCH + i8 * 16) = v;
            }
        }
        __syncthreads();

        // ---- 4 k16 steps ----
        #pragma unroll
        for (int ks = 0; ks < 4; ks++) {
            uint32_t Ah[4][4], Al[4][4], Bh[4][2], Bl[4][2];
            #pragma unroll
            for (int i = 0; i < 4; i++) {
                uint32_t off = (a_row + i * 16) * SPITCH + (ks * 16 + a_koff) * 2;
                ldsm4(Ah[i], sbase + 0 * TILE_BYTES + off);
                ldsm4(Al[i], sbase + 1 * TILE_BYTES + off);
            }
            #pragma unroll
            for (int j2 = 0; j2 < 2; j2++) {
                uint32_t off = (b_n + j2 * 16) * SPITCH + (ks * 16 + b_koff) * 2;
                uint32_t tmp[4];
                ldsm4(tmp, sbase + 2 * TILE_BYTES + off);
                Bh[j2 * 2][0] = tmp[0]; Bh[j2 * 2][1] = tmp[1];
                Bh[j2 * 2 + 1][0] = tmp[2]; Bh[j2 * 2 + 1][1] = tmp[3];
                ldsm4(tmp, sbase + 3 * TILE_BYTES + off);
                Bl[j2 * 2][0] = tmp[0]; Bl[j2 * 2][1] = tmp[1];
                Bl[j2 * 2 + 1][0] = tmp[2]; Bl[j2 * 2 + 1][1] = tmp[3];
            }
            #pragma unroll
            for (int i = 0; i < 4; i++)
                #pragma unroll
                for (int j = 0; j < 4; j++) {
                    mma16816(C[i][j], Ah[i], Bh[j]);
                    mma16816(C[i][j], Ah[i], Bl[j]);
                    mma16816(C[i][j], Al[i], Bh[j]);
                }
        }
    }

    // ---- epilogue: fused bias + (MODE 0) head scatter ----
    int r = lid >> 2, cg = (lid & 3) * 2;
    #pragma unroll
    for (int i = 0; i < 4; i++) {
        int row0 = m0 + wm * 64 + i * 16 + r;
        int row1 = row0 + 8;
        #pragma unroll
        for (int j = 0; j < 4; j++) {
            int col = n0 + wn * 32 + j * 8 + cg;
            float b0 = bias[col], b1 = bias[col + 1];
            float2 v0 = make_float2(C[i][j][0] + b0, C[i][j][1] + b1);
            float2 v1 = make_float2(C[i][j][2] + b0, C[i][j][3] + b1);
            if (MODE == 0) {
                int n = col >> 6, d = col & 63;
                if (row0 < MROWS) {
                    int bi = row0 / CS, s = row0 - bi * CS;
                    *(float2*)(out + (((size_t)(bi * CNH + n)) * CS + s) * CDH + d) = v0;
                }
                if (row1 < MROWS) {
                    int bi = row1 / CS, s = row1 - bi * CS;
                    *(float2*)(out + (((size_t)(bi * CNH + n)) * CS + s) * CDH + d) = v1;
                }
            } else {
                if (row0 < MROWS) *(float2*)(out + (size_t)row0 * CHID + col) = v0;
                if (row1 < MROWS) *(float2*)(out + (size_t)row1 * CHID + col) = v1;
            }
        }
    }
}

// ============================================================================
// Flash attention with Shaw relative position bias (unchanged from R3 pass).
// ============================================================================
#define SQ_STRIDE 68
#define SR_STRIDE 132
#define FLASH_SMEM_FLOATS (4*64*SQ_STRIDE + 64*SR_STRIDE)

__global__ __launch_bounds__(256, 2) void flash_kernel(
    const float* __restrict__ posk, const float* __restrict__ posv)
{
    extern __shared__ float sm[];
    float* Qs  = sm;                              // [64][68]
    float* Rs  = Qs + 64 * SQ_STRIDE;             // [64][132]
    float* Ks  = Rs + 64 * SR_STRIDE;             // [64][68]
    float* Vs  = Ks + 64 * SQ_STRIDE;             // [64][68]
    float* Ps  = Vs + 64 * SQ_STRIDE;             // [64][68]
    float* PKs = Ks;                              // prologue overlay [129][68]

    int qt = blockIdx.x, hn = blockIdx.y, bb = blockIdx.z;
    int q0 = qt * 64;
    size_t head_off = ((size_t)(bb * CNH + hn)) * CS * CDH;
    const float* qbase = g_q + head_off;
    const float* kbase = g_k + head_off;
    const float* vbase = g_v + head_off;

    int tid = threadIdx.x;
    int tx = tid & 15, ty = tid >> 4;

    for (int idx = tid; idx < 64 * 64; idx += 256) {
        int r = idx >> 6, d = idx & 63;
        int qg = q0 + r;
        Qs[r * SQ_STRIDE + d] = (qg < CS) ? qbase[qg * CDH + d] : 0.f;
    }
    for (int idx = tid; idx < NREL * 64; idx += 256) {
        int j = idx >> 6, d = idx & 63;
        PKs[j * SQ_STRIDE + d] = posk[idx];
    }
    __syncthreads();

    for (int t = tid; t < 64 * 33; t += 256) {
        int qq = t / 33;
        int jg = t - qq * 33;
        int j0 = jg * 4;
        const float4* q4 = (const float4*)(Qs + qq * SQ_STRIDE);
        if (jg < 32) {
            const float4* p0 = (const float4*)(PKs + (j0 + 0) * SQ_STRIDE);
            const float4* p1 = (const float4*)(PKs + (j0 + 1) * SQ_STRIDE);
            const float4* p2 = (const float4*)(PKs + (j0 + 2) * SQ_STRIDE);
            const float4* p3 = (const float4*)(PKs + (j0 + 3) * SQ_STRIDE);
            float a0 = 0.f, a1 = 0.f, a2 = 0.f, a3 = 0.f;
            #pragma unroll
            for (int d4 = 0; d4 < 16; d4++) {
                float4 qv = q4[d4];
                float4 x;
                x = p0[d4]; a0 += qv.x*x.x + qv.y*x.y + qv.z*x.z + qv.w*x.w;
                x = p1[d4]; a1 += qv.x*x.x + qv.y*x.y + qv.z*x.z + qv.w*x.w;
                x = p2[d4]; a2 += qv.x*x.x + qv.y*x.y + qv.z*x.z + qv.w*x.w;
                x = p3[d4]; a3 += qv.x*x.x + qv.y*x.y + qv.z*x.z + qv.w*x.w;
            }
            Rs[qq * SR_STRIDE + j0 + 0] = a0;
            Rs[qq * SR_STRIDE + j0 + 1] = a1;
            Rs[qq * SR_STRIDE + j0 + 2] = a2;
            Rs[qq * SR_STRIDE + j0 + 3] = a3;
        } else {
            const float4* p0 = (const float4*)(PKs + 128 * SQ_STRIDE);
            float a0 = 0.f;
            #pragma unroll
            for (int d4 = 0; d4 < 16; d4++) {
                float4 qv = q4[d4];
                float4 x = p0[d4];
                a0 += qv.x*x.x + qv.y*x.y + qv.z*x.z + qv.w*x.w;
            }
            Rs[qq * SR_STRIDE + 128] = a0;
        }
    }

    float m_i[4], l_i[4], PL[4], PH[4], O[4][4];
    #pragma unroll
    for (int i = 0; i < 4; i++) {
        m_i[i] = -1e30f; l_i[i] = 0.f; PL[i] = 0.f; PH[i] = 0.f;
        #pragma unroll
        for (int j = 0; j < 4; j++) O[i][j] = 0.f;
    }

    const int NKT = (CS + 63) / 64;
    for (int kt = 0; kt < NKT; kt++) {
        __syncthreads();
        for (int idx = tid; idx < 64 * 64; idx += 256) {
            int r = idx >> 6, d = idx & 63;
            int kg = kt * 64 + r;
            float kv = 0.f, vv = 0.f;
            if (kg < CS) { kv = kbase[kg * CDH + d]; vv = vbase[kg * CDH + d]; }
            Ks[r * SQ_STRIDE + d] = kv;
            Vs[r * SQ_STRIDE + d] = vv;
        }
        __syncthreads();

        float s[4][4];
        #pragma unroll
        for (int i = 0; i < 4; i++)
            #pragma unroll
            for (int j = 0; j < 4; j++) s[i][j] = 0.f;
        #pragma unroll 8
        for (int d = 0; d < 64; d++) {
            float a[4], bv[4];
            #pragma unroll
            for (int i = 0; i < 4; i++) a[i] = Qs[(ty * 4 + i) * SQ_STRIDE + d];
            #pragma unroll
            for (int j = 0; j < 4; j++) bv[j] = Ks[(tx * 4 + j) * SQ_STRIDE + d];
            #pragma unroll
            for (int i = 0; i < 4; i++)
                #pragma unroll
                for (int j = 0; j < 4; j++) s[i][j] += a[i] * bv[j];
        }

        #pragma unroll
        for (int i = 0; i < 4; i++) {
            int qg = q0 + ty * 4 + i;
            #pragma unroll
            for (int j = 0; j < 4; j++) {
                int kg = kt * 64 + tx * 4 + j;
                int delta = kg - qg;
                int jc = delta < -64 ? 0 : (delta > 64 ? 128 : delta + 64);
                float val = (s[i][j] + Rs[(ty * 4 + i) * SR_STRIDE + jc]) * 0.125f;
                s[i][j] = (kg < CS) ? val : -1e30f;
            }
        }

        int diff = kt * 64 - q0;
        bool band = (diff >= -64 && diff <= 64);

        #pragma unroll
        for (int i = 0; i < 4; i++) {
            float tmax = fmaxf(fmaxf(s[i][0], s[i][1]), fmaxf(s[i][2], s[i][3]));
            #pragma unroll
            for (int off = 8; off >= 1; off >>= 1)
                tmax = fmaxf(tmax, __shfl_xor_sync(0xffffffffu, tmax, off));
            float mnew  = fmaxf(m_i[i], tmax);
            float alpha = __expf(m_i[i] - mnew);
            m_i[i] = mnew;
            int qg = q0 + ty * 4 + i;
            float psum = 0.f, plo = 0.f, phi = 0.f;
            #pragma unroll
            for (int j = 0; j < 4; j++) {
                float p = __expf(s[i][j] - mnew);
                s[i][j] = p;
                psum += p;
                if (band) {
                    int delta = (kt * 64 + tx * 4 + j) - qg;
                    if (delta <= -64) plo += p;
                    if (delta >=  64) phi += p;
                }
            }
            #pragma unroll
            for (int off = 8; off >= 1; off >>= 1)
                psum += __shfl_xor_sync(0xffffffffu, psum, off);
            if (band) {
                #pragma unroll
                for (int off = 8; off >= 1; off >>= 1) {
                    plo += __shfl_xor_sync(0xffffffffu, plo, off);
                    phi += __shfl_xor_sync(0xffffffffu, phi, off);
                }
            } else if (diff < -64) { plo = psum; phi = 0.f; }
            else                   { phi = psum; plo = 0.f; }

            l_i[i] = l_i[i] * alpha + psum;
            PL[i]  = PL[i]  * alpha + plo;
            PH[i]  = PH[i]  * alpha + phi;
            #pragma unroll
            for (int j = 0; j < 4; j++) O[i][j] *= alpha;
            #pragma unroll
            for (int j = 0; j < 4; j++)
                Ps[(ty * 4 + i) * SQ_STRIDE + tx * 4 + j] = s[i][j];
        }
        __syncthreads();

        #pragma unroll 8
        for (int kk = 0; kk < 64; kk++) {
            float a[4], v[4];
            #pragma unroll
            for (int i = 0; i < 4; i++) a[i] = Ps[(ty * 4 + i) * SQ_STRIDE + kk];
            #pragma unroll
            for (int j = 0; j < 4; j++) v[j] = Vs[kk * SQ_STRIDE + tx * 4 + j];
            #pragma unroll
            for (int i = 0; i < 4; i++)
                #pragma unroll
                for (int j = 0; j < 4; j++) O[i][j] += a[i] * v[j];
        }

        if (band) {
            #pragma unroll 4
            for (int kk = 0; kk < 64; kk++) {
                int kg = kt * 64 + kk;
                #pragma unroll
                for (int i = 0; i < 4; i++) {
                    int delta = kg - (q0 + ty * 4 + i);
                    if (delta > -64 && delta < 64) {
                        float p = Ps[(ty * 4 + i) * SQ_STRIDE + kk];
                        float4 pv = *(const float4*)(posv + (delta + 64) * 64 + tx * 4);
                        O[i][0] += p * pv.x; O[i][1] += p * pv.y;
                        O[i][2] += p * pv.z; O[i][3] += p * pv.w;
                    }
                }
            }
        }
    }

    #pragma unroll
    for (int i = 0; i < 4; i++) {
        int qg = q0 + ty * 4 + i;
        if (qg >= CS) continue;
        float inv = 1.f / l_i[i];
        int dg = tx * 4;
        float4 pv0   = *(const float4*)(posv + 0 * 64 + dg);
        float4 pv128 = *(const float4*)(posv + 128 * 64 + dg);
        float4 res;
        res.x = (O[i][0] + PL[i] * pv0.x + PH[i] * pv128.x) * inv;
        res.y = (O[i][1] + PL[i] * pv0.y + PH[i] * pv128.y) * inv;
        res.z = (O[i][2] + PL[i] * pv0.z + PH[i] * pv128.z) * inv;
        res.w = (O[i][3] + PL[i] * pv0.w + PH[i] * pv128.w) * inv;
        *(float4*)(g_hidden + ((size_t)(bb * CS + qg)) * CHID + hn * 64 + dg) = res;
    }
}

// ============================================================================
extern "C" void kernel_launch(void* const* d_in, const int* in_sizes, int n_in,
                              void* d_out, int out_size)
{
    const float* query = (const float*)d_in[0];
    const float* key   = (const float*)d_in[1];
    const float* value = (const float*)d_in[2];
    const float* Wq    = (const float*)d_in[3];
    const float* bq    = (const float*)d_in[4];
    const float* Wk    = (const float*)d_in[5];
    const float* bk    = (const float*)d_in[6];
    const float* Wv    = (const float*)d_in[7];
    const float* bv    = (const float*)d_in[8];
    const float* posk  = (const float*)d_in[9];
    const float* posv  = (const float*)d_in[10];
    const float* Wfc   = (const float*)d_in[11];
    const float* bfc   = (const float*)d_in[12];
    float* out = (float*)d_out;

    float *gq, *gk, *gv, *gh;
    __nv_bfloat16 *xh, *xl, *wh, *wl;
    cudaGetSymbolAddress((void**)&gq, g_q);
    cudaGetSymbolAddress((void**)&gk, g_k);
    cudaGetSymbolAddress((void**)&gv, g_v);
    cudaGetSymbolAddress((void**)&gh, g_hidden);
    cudaGetSymbolAddress((void**)&xh, g_xh);
    cudaGetSymbolAddress((void**)&xl, g_xl);
    cudaGetSymbolAddress((void**)&wh, g_wh);
    cudaGetSymbolAddress((void**)&wl, g_wl);

    cudaFuncSetAttribute(gemm_mma<0>, cudaFuncAttributeMaxDynamicSharedMemorySize, GEMM_SMEM_BYTES);
    cudaFuncSetAttribute(gemm_mma<1>, cudaFuncAttributeMaxDynamicSharedMemorySize, GEMM_SMEM_BYTES);

    const int nX = MROWS * CHID;
    const int nW = CHID * CHID;
    dim3 ggrid((MROWS + 127) / 128, CHID / 128);   // 47 x 8

    // Q projection
    cvt_split<<<(nX + 255) / 256, 256>>>(query, xh, xl, nX);
    cvt_w_proj<<<(nW + 255) / 256, 256>>>(Wq, wh, wl);
    gemm_mma<0><<<ggrid, 256, GEMM_SMEM_BYTES>>>(xh, xl, wh, wl, bq, gq);
    // K projection
    cvt_split<<<(nX + 255) / 256, 256>>>(key, xh, xl, nX);
    cvt_w_proj<<<(nW + 255) / 256, 256>>>(Wk, wh, wl);
    gemm_mma<0><<<ggrid, 256, GEMM_SMEM_BYTES>>>(xh, xl, wh, wl, bk, gk);
    // V projection
    cvt_split<<<(nX + 255) / 256, 256>>>(value, xh, xl, nX);
    cvt_w_proj<<<(nW + 255) / 256, 256>>>(Wv, wh, wl);
    gemm_mma<0><<<ggrid, 256, GEMM_SMEM_BYTES>>>(xh, xl, wh, wl, bv, gv);

    // attention
    int smem_bytes = FLASH_SMEM_FLOATS * (int)sizeof(float);   // 103,424 B
    cudaFuncSetAttribute(flash_kernel,
                         cudaFuncAttributeMaxDynamicSharedMemorySize, smem_bytes);
    flash_kernel<<<dim3((CS + 63) / 64, CNH, CB), 256, smem_bytes>>>(posk, posv);

    // output projection
    cvt_split<<<(nX + 255) / 256, 256>>>(gh, xh, xl, nX);
    cvt_w_fc<<<(nW + 255) / 256, 256>>>(Wfc, wh, wl);
    gemm_mma<1><<<ggrid, 256, GEMM_SMEM_BYTES>>>(xh, xl, wh, wl, bfc, out);
}